// round 5
// baseline (speedup 1.0000x reference)
#include <cuda_runtime.h>
#include <math.h>

#define BB 16
#define NL 48
#define NP 256
#define DD 128
#define NROW_L (BB*NL)    /* 768  */
#define NROW_P (BB*NP)    /* 4096 */
#define NPAIR  (BB*NL*NP) /* 196608 */

#define PI_OFF 0
#define SG_OFF (NPAIR*10)
#define MU_OFF (NPAIR*20)
#define DI_OFF (NPAIR*30)
#define CM_OFF (NPAIR*31)

__device__ float2 g_ueu[NROW_L*DD];   // {u, exp(u)} per (b,l,d)
__device__ float2 g_w  [BB*DD*NP];    // [b][d][p] {v, exp(v)}
__device__ float4 g_xl [NROW_L];      // x,y,z,|x|^2 (zeros if masked)
__device__ float4 g_xp [NROW_P];

// ---------------- PTX helpers ----------------
__device__ __forceinline__ unsigned long long pk2(float x) {
    unsigned long long r;
    asm("mov.b64 %0, {%1, %1};" : "=l"(r) : "f"(x));
    return r;
}
#define FFMA2(acc, a, b) \
    asm volatile("fma.rn.f32x2 %0, %1, %2, %0;" : "+l"(acc) : "l"(a), "l"(b))
#define LDSV2(lo, hi, addr, IMM) \
    asm volatile("ld.shared.v2.b64 {%0, %1}, [%2+" IMM "];" \
                 : "=l"(lo), "=l"(hi) : "r"(addr))
#define UNPK(lo, hi, v) \
    asm("mov.b64 {%0, %1}, %2;" : "=f"(lo), "=f"(hi) : "l"(v))

__device__ __forceinline__ unsigned smem_u32(const void* p) {
    return (unsigned)__cvta_generic_to_shared(p);
}

// ---------------- fused prep ----------------
__global__ __launch_bounds__(DD) void k_pre(
    const float* __restrict__ hl, const float* __restrict__ hp,
    const float* __restrict__ pos_l, const float* __restrict__ pos_p,
    const int* __restrict__ num_l, const int* __restrict__ num_p,
    const float* __restrict__ W1, const float* __restrict__ b1,
    const float* __restrict__ gamma, const float* __restrict__ beta,
    const float* __restrict__ mean, const float* __restrict__ var)
{
    __shared__ int cl[BB+1], cp[BB+1];
    __shared__ float xs[8][DD];
    __shared__ float2 tt[DD][9];
    const int tid = threadIdx.x;

    if (tid == 0) {
        cl[0] = 0; cp[0] = 0;
        #pragma unroll
        for (int i = 0; i < BB; i++) { cl[i+1] = cl[i] + num_l[i]; cp[i+1] = cp[i] + num_p[i]; }
    }
    __syncthreads();

    const float kf = gamma[tid] * rsqrtf(var[tid] + 1e-5f);

    if (blockIdx.x < NROW_L/8) {
        const int r0 = blockIdx.x * 8;
        const int b  = r0 / NL, l0 = r0 % NL;
        const int nl = num_l[b];
        #pragma unroll
        for (int i = 0; i < 8; i++) {
            float v = 0.f;
            if (l0 + i < nl) v = hl[(cl[b] + l0 + i) * DD + tid];
            xs[i][tid] = v;
        }
        __syncthreads();
        float acc[8] = {0,0,0,0,0,0,0,0};
        #pragma unroll 4
        for (int d = 0; d < DD; d++) {
            float w = W1[d * DD + tid];
            #pragma unroll
            for (int i = 0; i < 8; i++) acc[i] = fmaf(xs[i][d], w, acc[i]);
        }
        const float c = (b1[tid] - mean[tid]) * kf + beta[tid];
        #pragma unroll
        for (int i = 0; i < 8; i++) {
            float u = fmaf(acc[i], kf, c);
            g_ueu[(r0 + i) * DD + tid] = make_float2(u, __expf(u));
        }
        if (tid < 8) {
            int l = l0 + tid;
            float4 o = make_float4(0.f, 0.f, 0.f, 0.f);
            if (l < nl) {
                int s = cl[b] + l;
                float x = pos_l[s*3+0], y = pos_l[s*3+1], z = pos_l[s*3+2];
                o = make_float4(x, y, z, x*x + y*y + z*z);
            }
            g_xl[r0 + tid] = o;
        }
    } else {
        const int r0 = (blockIdx.x - NROW_L/8) * 8;
        const int b  = r0 / NP, p0 = r0 % NP;
        const int np = num_p[b];
        #pragma unroll
        for (int i = 0; i < 8; i++) {
            float v = 0.f;
            if (p0 + i < np) v = hp[(cp[b] + p0 + i) * DD + tid];
            xs[i][tid] = v;
        }
        __syncthreads();
        float acc[8] = {0,0,0,0,0,0,0,0};
        const float* W1b = W1 + DD * DD;
        #pragma unroll 4
        for (int d = 0; d < DD; d++) {
            float w = W1b[d * DD + tid];
            #pragma unroll
            for (int i = 0; i < 8; i++) acc[i] = fmaf(xs[i][d], w, acc[i]);
        }
        #pragma unroll
        for (int i = 0; i < 8; i++) {
            float v = acc[i] * kf;
            tt[tid][i] = make_float2(v, __expf(v));
        }
        __syncthreads();
        #pragma unroll
        for (int it = 0; it < 8; it++) {
            int idx = tid + DD * it;
            int f = idx >> 3, pl = idx & 7;
            g_w[(b * DD + f) * NP + p0 + pl] = tt[f][pl];
        }
        if (tid < 8) {
            int p = p0 + tid;
            float4 o = make_float4(0.f, 0.f, 0.f, 0.f);
            if (p < np) {
                int s = cp[b] + p;
                float x = pos_p[s*3+0], y = pos_p[s*3+1], z = pos_p[s*3+2];
                o = make_float4(x, y, z, x*x + y*y + z*z);
            }
            g_xp[r0 + tid] = o;
        }
    }
}

// ---------------- main: ONE l-row per block, 5 blocks/SM ----------------
__global__ __launch_bounds__(NP, 5) void k_main(
    const float* __restrict__ W_pi, const float* __restrict__ b_pi,
    const float* __restrict__ W_sg, const float* __restrict__ b_sg,
    const float* __restrict__ W_mu, const float* __restrict__ b_mu,
    const int* __restrict__ num_l, const int* __restrict__ num_p,
    float* __restrict__ out)
{
    __shared__ __align__(16) float2 ueu[DD];      // {u, exp(u)} for this l row
    __shared__ __align__(16) float2 Wsp[DD][16];  // [d][jj] = {W[2jj], W[2jj+1]}
    __shared__ float  bias[32];

    const int tid = threadIdx.x;
    const int bl  = blockIdx.x;
    const int b   = bl / NL;
    const int l   = bl % NL;

    if (tid < DD) ueu[tid] = g_ueu[bl * DD + tid];
    for (int idx = tid; idx < DD * 15; idx += NP) {
        int d = idx / 15, jj = idx % 15;
        float a, bv;
        if (jj < 5)       { a = W_pi[d*10 + 2*jj];      bv = W_pi[d*10 + 2*jj + 1]; }
        else if (jj < 10) { a = W_sg[d*10 + 2*(jj-5)];  bv = W_sg[d*10 + 2*(jj-5) + 1]; }
        else              { a = W_mu[d*10 + 2*(jj-10)]; bv = W_mu[d*10 + 2*(jj-10) + 1]; }
        Wsp[d][jj] = make_float2(a, bv);
    }
    if (tid < 10) {
        bias[tid     ] = b_pi[tid];
        bias[tid + 10] = b_sg[tid];
        bias[tid + 20] = b_mu[tid];
    }
    __syncthreads();

    const int p = tid;
    const float m = (l < num_l[b] && p < num_p[b]) ? 1.f : 0.f;

    unsigned long long acc[15];
    #pragma unroll
    for (int jj = 0; jj < 15; jj++) acc[jj] = 0ull;

    const float2* __restrict__ wrow = g_w + (size_t)(b * DD) * NP + p;
    const unsigned wbase = smem_u32(&Wsp[0][0]);
    const unsigned ubase = smem_u32(&ueu[0]);

    #pragma unroll 4
    for (int d = 0; d < DD; d++) {
        float2 w = wrow[d * NP];                  // LDG.64 {v, exp(v)}
        float2 a;                                 // LDS.64 broadcast {u, exp(u)}
        asm("ld.shared.v2.f32 {%0,%1}, [%2];" : "=f"(a.x), "=f"(a.y) : "r"(ubase + d*8));
        float uv = a.x + w.x;
        float t  = fmaf(a.y, w.y, -1.f);
        float e  = (uv > 0.f) ? uv : t;           // elu(u+v) via exp(u)*exp(v)-1
        unsigned long long ep = pk2(e);

        const unsigned wa = wbase + d * 128;      // 16 float2 = 128B per row
        unsigned long long q0, q1;
        LDSV2(q0, q1, wa, "0");
        FFMA2(acc[0], ep, q0); FFMA2(acc[1], ep, q1);
        LDSV2(q0, q1, wa, "16");
        FFMA2(acc[2], ep, q0); FFMA2(acc[3], ep, q1);
        LDSV2(q0, q1, wa, "32");
        FFMA2(acc[4], ep, q0); FFMA2(acc[5], ep, q1);
        LDSV2(q0, q1, wa, "48");
        FFMA2(acc[6], ep, q0); FFMA2(acc[7], ep, q1);
        LDSV2(q0, q1, wa, "64");
        FFMA2(acc[8], ep, q0); FFMA2(acc[9], ep, q1);
        LDSV2(q0, q1, wa, "80");
        FFMA2(acc[10], ep, q0); FFMA2(acc[11], ep, q1);
        LDSV2(q0, q1, wa, "96");
        FFMA2(acc[12], ep, q0); FFMA2(acc[13], ep, q1);
        LDSV2(q0, q1, wa, "112");
        FFMA2(acc[14], ep, q0);
        (void)q1;
    }

    // ---------------- epilogue ----------------
    float z[30];
    #pragma unroll
    for (int jj = 0; jj < 15; jj++) UNPK(z[2*jj], z[2*jj+1], acc[jj]);

    float zmax = -1e30f;
    #pragma unroll
    for (int j = 0; j < 10; j++) { z[j] += bias[j]; zmax = fmaxf(zmax, z[j]); }
    float ssum = 0.f;
    #pragma unroll
    for (int j = 0; j < 10; j++) { float e = __expf(z[j] - zmax); z[j] = e; ssum += e; }
    float inv = m / ssum;

    const int base = (bl * NP + p) * 10;
    float2* opi = (float2*)(out + PI_OFF + base);
    float2* osg = (float2*)(out + SG_OFF + base);
    float2* omu = (float2*)(out + MU_OFF + base);
    #pragma unroll
    for (int j = 0; j < 5; j++)
        opi[j] = make_float2(z[2*j] * inv, z[2*j+1] * inv);
    #pragma unroll
    for (int j = 0; j < 10; j++) {
        float t = z[10 + j] + bias[10 + j];
        float e = (t > 0.f) ? t : (__expf(t) - 1.f);
        z[10 + j] = (e + 1.1f) * m;
    }
    #pragma unroll
    for (int j = 0; j < 5; j++) osg[j] = make_float2(z[10+2*j], z[11+2*j]);
    #pragma unroll
    for (int j = 0; j < 10; j++) {
        float t = z[20 + j] + bias[20 + j];
        float e = (t > 0.f) ? t : (__expf(t) - 1.f);
        z[20 + j] = (e + 1.0f) * m;
    }
    #pragma unroll
    for (int j = 0; j < 5; j++) omu[j] = make_float2(z[20+2*j], z[21+2*j]);

    // distance + mask
    float4 xp = g_xp[b * NP + p];
    float4 xl = g_xl[bl];
    float d2 = xl.w + xp.w - 2.f * (xl.x*xp.x + xl.y*xp.y + xl.z*xp.z);
    out[DI_OFF + bl * NP + p] = sqrtf(fmaxf(d2, 0.f)) * m;
    out[CM_OFF + bl * NP + p] = m;
}

extern "C" void kernel_launch(void* const* d_in, const int* in_sizes, int n_in,
                              void* d_out, int out_size)
{
    int s = 0;
    if (n_in >= 20 && in_sizes[6] == 1 && in_sizes[7] == 1) s = 2;

    const float* hl    = (const float*)d_in[0];
    const float* hp    = (const float*)d_in[1];
    const float* pos_l = (const float*)d_in[2];
    const float* pos_p = (const float*)d_in[3];
    const int*   num_l = (const int*)  d_in[4];
    const int*   num_p = (const int*)  d_in[5];
    const float* W1    = (const float*)d_in[6 + s];
    const float* b1    = (const float*)d_in[7 + s];
    const float* gamma = (const float*)d_in[8 + s];
    const float* beta  = (const float*)d_in[9 + s];
    const float* mean  = (const float*)d_in[10 + s];
    const float* var   = (const float*)d_in[11 + s];
    const float* W_pi  = (const float*)d_in[12 + s];
    const float* b_pi  = (const float*)d_in[13 + s];
    const float* W_sg  = (const float*)d_in[14 + s];
    const float* b_sg  = (const float*)d_in[15 + s];
    const float* W_mu  = (const float*)d_in[16 + s];
    const float* b_mu  = (const float*)d_in[17 + s];
    float* out = (float*)d_out;

    k_pre <<<NROW_L/8 + NROW_P/8, DD>>>(hl, hp, pos_l, pos_p, num_l, num_p,
                                        W1, b1, gamma, beta, mean, var);
    k_main<<<BB * NL, NP>>>(W_pi, b_pi, W_sg, b_sg, W_mu, b_mu,
                            num_l, num_p, out);
}

// round 7
// speedup vs baseline: 1.4665x; 1.4665x over previous
#include <cuda_runtime.h>
#include <math.h>

#define BB 16
#define NL 48
#define NP 256
#define DD 128
#define NROW_L (BB*NL)    /* 768  */
#define NROW_P (BB*NP)    /* 4096 */
#define NPAIR  (BB*NL*NP) /* 196608 */

#define PI_OFF 0
#define SG_OFF (NPAIR*10)
#define MU_OFF (NPAIR*20)
#define DI_OFF (NPAIR*30)
#define CM_OFF (NPAIR*31)

__device__ float2 g_ueu[NROW_L*DD];   // {u, exp(u)} per (b,l,d)
__device__ float2 g_w  [BB*DD*NP];    // [b][d][p] {v, exp(v)}
__device__ float4 g_xl [NROW_L];      // x,y,z,|x|^2 (zeros if masked)
__device__ float4 g_xp [NROW_P];

// ---------------- PTX helpers ----------------
// NOTE: FFMA2 / pk2 / UNPK are NON-volatile: pure value ops, ptxas schedules
// them freely by data dependence (volatile froze the whole inner loop into
// program order and capped issue at ~40% in R2-R5).
__device__ __forceinline__ unsigned long long pk2(float x) {
    unsigned long long r;
    asm("mov.b64 %0, {%1, %1};" : "=l"(r) : "f"(x));
    return r;
}
#define FFMA2(acc, a, b) \
    asm("fma.rn.f32x2 %0, %1, %2, %0;" : "+l"(acc) : "l"(a), "l"(b))
// LDS stays volatile (no memory clobber): keeps it below __syncthreads, but
// normal loads / non-volatile asm still move across it.
#define LDSV2(lo, hi, addr, IMM) \
    asm volatile("ld.shared.v2.b64 {%0, %1}, [%2+" IMM "];" \
                 : "=l"(lo), "=l"(hi) : "r"(addr))
#define UNPK(lo, hi, v) \
    asm("mov.b64 {%0, %1}, %2;" : "=f"(lo), "=f"(hi) : "l"(v))

__device__ __forceinline__ unsigned smem_u32(const void* p) {
    return (unsigned)__cvta_generic_to_shared(p);
}

// ---------------- fused prep ----------------
__global__ __launch_bounds__(DD) void k_pre(
    const float* __restrict__ hl, const float* __restrict__ hp,
    const float* __restrict__ pos_l, const float* __restrict__ pos_p,
    const int* __restrict__ num_l, const int* __restrict__ num_p,
    const float* __restrict__ W1, const float* __restrict__ b1,
    const float* __restrict__ gamma, const float* __restrict__ beta,
    const float* __restrict__ mean, const float* __restrict__ var)
{
    __shared__ int cl[BB+1], cp[BB+1];
    __shared__ float xs[8][DD];
    __shared__ float2 tt[DD][9];
    const int tid = threadIdx.x;

    if (tid == 0) {
        cl[0] = 0; cp[0] = 0;
        #pragma unroll
        for (int i = 0; i < BB; i++) { cl[i+1] = cl[i] + num_l[i]; cp[i+1] = cp[i] + num_p[i]; }
    }
    __syncthreads();

    const float kf = gamma[tid] * rsqrtf(var[tid] + 1e-5f);

    if (blockIdx.x < NROW_L/8) {
        const int r0 = blockIdx.x * 8;
        const int b  = r0 / NL, l0 = r0 % NL;
        const int nl = num_l[b];
        #pragma unroll
        for (int i = 0; i < 8; i++) {
            float v = 0.f;
            if (l0 + i < nl) v = hl[(cl[b] + l0 + i) * DD + tid];
            xs[i][tid] = v;
        }
        __syncthreads();
        float acc[8] = {0,0,0,0,0,0,0,0};
        #pragma unroll 4
        for (int d = 0; d < DD; d++) {
            float w = W1[d * DD + tid];
            #pragma unroll
            for (int i = 0; i < 8; i++) acc[i] = fmaf(xs[i][d], w, acc[i]);
        }
        const float c = (b1[tid] - mean[tid]) * kf + beta[tid];
        #pragma unroll
        for (int i = 0; i < 8; i++) {
            float u = fmaf(acc[i], kf, c);
            g_ueu[(r0 + i) * DD + tid] = make_float2(u, __expf(u));
        }
        if (tid < 8) {
            int l = l0 + tid;
            float4 o = make_float4(0.f, 0.f, 0.f, 0.f);
            if (l < nl) {
                int s = cl[b] + l;
                float x = pos_l[s*3+0], y = pos_l[s*3+1], z = pos_l[s*3+2];
                o = make_float4(x, y, z, x*x + y*y + z*z);
            }
            g_xl[r0 + tid] = o;
        }
    } else {
        const int r0 = (blockIdx.x - NROW_L/8) * 8;
        const int b  = r0 / NP, p0 = r0 % NP;
        const int np = num_p[b];
        #pragma unroll
        for (int i = 0; i < 8; i++) {
            float v = 0.f;
            if (p0 + i < np) v = hp[(cp[b] + p0 + i) * DD + tid];
            xs[i][tid] = v;
        }
        __syncthreads();
        float acc[8] = {0,0,0,0,0,0,0,0};
        const float* W1b = W1 + DD * DD;
        #pragma unroll 4
        for (int d = 0; d < DD; d++) {
            float w = W1b[d * DD + tid];
            #pragma unroll
            for (int i = 0; i < 8; i++) acc[i] = fmaf(xs[i][d], w, acc[i]);
        }
        #pragma unroll
        for (int i = 0; i < 8; i++) {
            float v = acc[i] * kf;
            tt[tid][i] = make_float2(v, __expf(v));
        }
        __syncthreads();
        #pragma unroll
        for (int it = 0; it < 8; it++) {
            int idx = tid + DD * it;
            int f = idx >> 3, pl = idx & 7;
            g_w[(b * DD + f) * NP + p0 + pl] = tt[f][pl];
        }
        if (tid < 8) {
            int p = p0 + tid;
            float4 o = make_float4(0.f, 0.f, 0.f, 0.f);
            if (p < np) {
                int s = cp[b] + p;
                float x = pos_p[s*3+0], y = pos_p[s*3+1], z = pos_p[s*3+2];
                o = make_float4(x, y, z, x*x + y*y + z*z);
            }
            g_xp[r0 + tid] = o;
        }
    }
}

// ---------------- epilogue for one (l,p) ----------------
__device__ __forceinline__ void epi(
    const unsigned long long* acc, const float* bias, float m,
    int bl, int p, float* __restrict__ out)
{
    float z[30];
    #pragma unroll
    for (int jj = 0; jj < 15; jj++) UNPK(z[2*jj], z[2*jj+1], acc[jj]);

    float zmax = -1e30f;
    #pragma unroll
    for (int j = 0; j < 10; j++) { z[j] += bias[j]; zmax = fmaxf(zmax, z[j]); }
    float ssum = 0.f;
    #pragma unroll
    for (int j = 0; j < 10; j++) { float e = __expf(z[j] - zmax); z[j] = e; ssum += e; }
    float inv = m / ssum;

    const int base = (bl * NP + p) * 10;
    float2* opi = (float2*)(out + PI_OFF + base);
    float2* osg = (float2*)(out + SG_OFF + base);
    float2* omu = (float2*)(out + MU_OFF + base);
    #pragma unroll
    for (int j = 0; j < 5; j++)
        opi[j] = make_float2(z[2*j] * inv, z[2*j+1] * inv);
    #pragma unroll
    for (int j = 0; j < 10; j++) {
        float t = z[10 + j] + bias[10 + j];
        float e = (t > 0.f) ? t : (__expf(t) - 1.f);
        z[10 + j] = (e + 1.1f) * m;
    }
    #pragma unroll
    for (int j = 0; j < 5; j++) osg[j] = make_float2(z[10+2*j], z[11+2*j]);
    #pragma unroll
    for (int j = 0; j < 10; j++) {
        float t = z[20 + j] + bias[20 + j];
        float e = (t > 0.f) ? t : (__expf(t) - 1.f);
        z[20 + j] = (e + 1.0f) * m;
    }
    #pragma unroll
    for (int j = 0; j < 5; j++) omu[j] = make_float2(z[20+2*j], z[21+2*j]);
}

// ---------------- main: 2 l-rows per block ----------------
__global__ __launch_bounds__(NP, 3) void k_main(
    const float* __restrict__ W_pi, const float* __restrict__ b_pi,
    const float* __restrict__ W_sg, const float* __restrict__ b_sg,
    const float* __restrict__ W_mu, const float* __restrict__ b_mu,
    const int* __restrict__ num_l, const int* __restrict__ num_p,
    float* __restrict__ out)
{
    __shared__ __align__(16) float2 ueu[2][DD];
    __shared__ __align__(16) float2 Wsp[DD][16];
    __shared__ float  bias[32];

    const int tid = threadIdx.x;
    const int bl0 = blockIdx.x * 2;
    const int b   = bl0 / NL;
    const int l0  = bl0 % NL;

    {
        int l = tid >> 7, d = tid & (DD-1);
        ueu[l][d] = g_ueu[(bl0 + l) * DD + d];
    }
    for (int idx = tid; idx < DD * 15; idx += NP) {
        int d = idx / 15, jj = idx % 15;
        float a, bv;
        if (jj < 5)       { a = W_pi[d*10 + 2*jj];      bv = W_pi[d*10 + 2*jj + 1]; }
        else if (jj < 10) { a = W_sg[d*10 + 2*(jj-5)];  bv = W_sg[d*10 + 2*(jj-5) + 1]; }
        else              { a = W_mu[d*10 + 2*(jj-10)]; bv = W_mu[d*10 + 2*(jj-10) + 1]; }
        Wsp[d][jj] = make_float2(a, bv);
    }
    if (tid < 10) {
        bias[tid     ] = b_pi[tid];
        bias[tid + 10] = b_sg[tid];
        bias[tid + 20] = b_mu[tid];
    }
    __syncthreads();

    const int p = tid;
    const int mp = (p < num_p[b]);
    const int nl = num_l[b];
    const float m0 = (l0     < nl && mp) ? 1.f : 0.f;
    const float m1 = (l0 + 1 < nl && mp) ? 1.f : 0.f;

    unsigned long long acc0[15], acc1[15];
    #pragma unroll
    for (int jj = 0; jj < 15; jj++) { acc0[jj] = 0ull; acc1[jj] = 0ull; }

    const float2* __restrict__ wrow = g_w + (size_t)(b * DD) * NP + p;
    const unsigned wbase = smem_u32(&Wsp[0][0]);
    const unsigned ubase = smem_u32(&ueu[0][0]);

    #pragma unroll 4
    for (int d = 0; d < DD; d++) {
        float2 w = wrow[d * NP];                  // LDG.64 {v, exp(v)} — hoistable
        float2 a0, a1;                            // LDS.64 broadcast
        asm volatile("ld.shared.v2.f32 {%0,%1}, [%2];" : "=f"(a0.x), "=f"(a0.y) : "r"(ubase + d*8));
        asm volatile("ld.shared.v2.f32 {%0,%1}, [%2];" : "=f"(a1.x), "=f"(a1.y) : "r"(ubase + DD*8 + d*8));
        float uv0 = a0.x + w.x, t0 = fmaf(a0.y, w.y, -1.f);
        float uv1 = a1.x + w.x, t1 = fmaf(a1.y, w.y, -1.f);
        float e0 = (uv0 > 0.f) ? uv0 : t0;
        float e1 = (uv1 > 0.f) ? uv1 : t1;
        unsigned long long e0p = pk2(e0), e1p = pk2(e1);

        const unsigned wa = wbase + d * 128;
        unsigned long long q0, q1;
        LDSV2(q0, q1, wa, "0");
        FFMA2(acc0[0], e0p, q0); FFMA2(acc1[0], e1p, q0);
        FFMA2(acc0[1], e0p, q1); FFMA2(acc1[1], e1p, q1);
        LDSV2(q0, q1, wa, "16");
        FFMA2(acc0[2], e0p, q0); FFMA2(acc1[2], e1p, q0);
        FFMA2(acc0[3], e0p, q1); FFMA2(acc1[3], e1p, q1);
        LDSV2(q0, q1, wa, "32");
        FFMA2(acc0[4], e0p, q0); FFMA2(acc1[4], e1p, q0);
        FFMA2(acc0[5], e0p, q1); FFMA2(acc1[5], e1p, q1);
        LDSV2(q0, q1, wa, "48");
        FFMA2(acc0[6], e0p, q0); FFMA2(acc1[6], e1p, q0);
        FFMA2(acc0[7], e0p, q1); FFMA2(acc1[7], e1p, q1);
        LDSV2(q0, q1, wa, "64");
        FFMA2(acc0[8], e0p, q0); FFMA2(acc1[8], e1p, q0);
        FFMA2(acc0[9], e0p, q1); FFMA2(acc1[9], e1p, q1);
        LDSV2(q0, q1, wa, "80");
        FFMA2(acc0[10], e0p, q0); FFMA2(acc1[10], e1p, q0);
        FFMA2(acc0[11], e0p, q1); FFMA2(acc1[11], e1p, q1);
        LDSV2(q0, q1, wa, "96");
        FFMA2(acc0[12], e0p, q0); FFMA2(acc1[12], e1p, q0);
        FFMA2(acc0[13], e0p, q1); FFMA2(acc1[13], e1p, q1);
        LDSV2(q0, q1, wa, "112");
        FFMA2(acc0[14], e0p, q0); FFMA2(acc1[14], e1p, q0);
        (void)q1;
    }

    epi(acc0, bias, m0, bl0,     p, out);
    epi(acc1, bias, m1, bl0 + 1, p, out);

    float4 xp = g_xp[b * NP + p];
    {
        float4 xl = g_xl[bl0];
        float d2 = xl.w + xp.w - 2.f * (xl.x*xp.x + xl.y*xp.y + xl.z*xp.z);
        out[DI_OFF + bl0 * NP + p] = sqrtf(fmaxf(d2, 0.f)) * m0;
        out[CM_OFF + bl0 * NP + p] = m0;
    }
    {
        float4 xl = g_xl[bl0 + 1];
        float d2 = xl.w + xp.w - 2.f * (xl.x*xp.x + xl.y*xp.y + xl.z*xp.z);
        out[DI_OFF + (bl0+1) * NP + p] = sqrtf(fmaxf(d2, 0.f)) * m1;
        out[CM_OFF + (bl0+1) * NP + p] = m1;
    }
}

extern "C" void kernel_launch(void* const* d_in, const int* in_sizes, int n_in,
                              void* d_out, int out_size)
{
    int s = 0;
    if (n_in >= 20 && in_sizes[6] == 1 && in_sizes[7] == 1) s = 2;

    const float* hl    = (const float*)d_in[0];
    const float* hp    = (const float*)d_in[1];
    const float* pos_l = (const float*)d_in[2];
    const float* pos_p = (const float*)d_in[3];
    const int*   num_l = (const int*)  d_in[4];
    const int*   num_p = (const int*)  d_in[5];
    const float* W1    = (const float*)d_in[6 + s];
    const float* b1    = (const float*)d_in[7 + s];
    const float* gamma = (const float*)d_in[8 + s];
    const float* beta  = (const float*)d_in[9 + s];
    const float* mean  = (const float*)d_in[10 + s];
    const float* var   = (const float*)d_in[11 + s];
    const float* W_pi  = (const float*)d_in[12 + s];
    const float* b_pi  = (const float*)d_in[13 + s];
    const float* W_sg  = (const float*)d_in[14 + s];
    const float* b_sg  = (const float*)d_in[15 + s];
    const float* W_mu  = (const float*)d_in[16 + s];
    const float* b_mu  = (const float*)d_in[17 + s];
    float* out = (float*)d_out;

    k_pre <<<NROW_L/8 + NROW_P/8, DD>>>(hl, hp, pos_l, pos_p, num_l, num_p,
                                        W1, b1, gamma, beta, mean, var);
    k_main<<<BB * NL / 2, NP>>>(W_pi, b_pi, W_sg, b_sg, W_mu, b_mu,
                                num_l, num_p, out);
}

// round 8
// speedup vs baseline: 2.2390x; 1.5268x over previous
#include <cuda_runtime.h>
#include <stdint.h>
#include <math.h>

#define BB 16
#define NL 48
#define NP 256
#define DD 128
#define NROW_L (BB*NL)    /* 768  */
#define NROW_P (BB*NP)    /* 4096 */
#define NPAIR  (BB*NL*NP) /* 196608 */

#define PI_OFF 0
#define SG_OFF (NPAIR*10)
#define MU_OFF (NPAIR*20)
#define DI_OFF (NPAIR*30)
#define CM_OFF (NPAIR*31)

// dynamic smem layout for k_main
#define SM_UEU   0                       /* float2[256]         2048 B  */
#define SM_BS    2048                    /* uint2[2048]        16384 B  */
#define SM_CSM   (2048+16384)            /* float[512*34]      69632 B  */
#define SM_BIAS  (2048+16384+69632)      /* float[32]            128 B  */
#define SM_TOTAL (2048+16384+69632+128)  /* 88192 B */
#define CPAD 34                          /* Csm row stride in floats */

__device__ float2 g_ueu[NROW_L*DD];   // {u, exp(u)} per (b,l,d)
__device__ float2 g_w  [BB*DD*NP];    // [b][d][p] {v, exp(v)}
__device__ float4 g_xl [NROW_L];      // x,y,z,|x|^2 (zeros if masked)
__device__ float4 g_xp [NROW_P];

__device__ __forceinline__ uint32_t cvt_tf32(float f) {
    uint32_t r;
    asm("cvt.rna.tf32.f32 %0, %1;" : "=r"(r) : "f"(f));
    return r;
}
__device__ __forceinline__ void mma8(float* c, const uint32_t* a, const uint32_t* b) {
    asm("mma.sync.aligned.m16n8k8.row.col.f32.tf32.tf32.f32 "
        "{%0,%1,%2,%3}, {%4,%5,%6,%7}, {%8,%9}, {%0,%1,%2,%3};"
        : "+f"(c[0]), "+f"(c[1]), "+f"(c[2]), "+f"(c[3])
        : "r"(a[0]), "r"(a[1]), "r"(a[2]), "r"(a[3]), "r"(b[0]), "r"(b[1]));
}
// elu(u+v) using exp(u)*exp(v)-1 for the negative branch
__device__ __forceinline__ float elu2(float2 u, float2 w) {
    float uv = u.x + w.x;
    float t  = fmaf(u.y, w.y, -1.f);
    return (uv > 0.f) ? uv : t;
}

// ---------------- fused prep (unchanged, working, ~0.6us) ----------------
__global__ __launch_bounds__(DD) void k_pre(
    const float* __restrict__ hl, const float* __restrict__ hp,
    const float* __restrict__ pos_l, const float* __restrict__ pos_p,
    const int* __restrict__ num_l, const int* __restrict__ num_p,
    const float* __restrict__ W1, const float* __restrict__ b1,
    const float* __restrict__ gamma, const float* __restrict__ beta,
    const float* __restrict__ mean, const float* __restrict__ var)
{
    __shared__ int cl[BB+1], cp[BB+1];
    __shared__ float xs[8][DD];
    __shared__ float2 tt[DD][9];
    const int tid = threadIdx.x;

    if (tid == 0) {
        cl[0] = 0; cp[0] = 0;
        #pragma unroll
        for (int i = 0; i < BB; i++) { cl[i+1] = cl[i] + num_l[i]; cp[i+1] = cp[i] + num_p[i]; }
    }
    __syncthreads();

    const float kf = gamma[tid] * rsqrtf(var[tid] + 1e-5f);

    if (blockIdx.x < NROW_L/8) {
        const int r0 = blockIdx.x * 8;
        const int b  = r0 / NL, l0 = r0 % NL;
        const int nl = num_l[b];
        #pragma unroll
        for (int i = 0; i < 8; i++) {
            float v = 0.f;
            if (l0 + i < nl) v = hl[(cl[b] + l0 + i) * DD + tid];
            xs[i][tid] = v;
        }
        __syncthreads();
        float acc[8] = {0,0,0,0,0,0,0,0};
        #pragma unroll 4
        for (int d = 0; d < DD; d++) {
            float w = W1[d * DD + tid];
            #pragma unroll
            for (int i = 0; i < 8; i++) acc[i] = fmaf(xs[i][d], w, acc[i]);
        }
        const float c = (b1[tid] - mean[tid]) * kf + beta[tid];
        #pragma unroll
        for (int i = 0; i < 8; i++) {
            float u = fmaf(acc[i], kf, c);
            g_ueu[(r0 + i) * DD + tid] = make_float2(u, __expf(u));
        }
        if (tid < 8) {
            int l = l0 + tid;
            float4 o = make_float4(0.f, 0.f, 0.f, 0.f);
            if (l < nl) {
                int s = cl[b] + l;
                float x = pos_l[s*3+0], y = pos_l[s*3+1], z = pos_l[s*3+2];
                o = make_float4(x, y, z, x*x + y*y + z*z);
            }
            g_xl[r0 + tid] = o;
        }
    } else {
        const int r0 = (blockIdx.x - NROW_L/8) * 8;
        const int b  = r0 / NP, p0 = r0 % NP;
        const int np = num_p[b];
        #pragma unroll
        for (int i = 0; i < 8; i++) {
            float v = 0.f;
            if (p0 + i < np) v = hp[(cp[b] + p0 + i) * DD + tid];
            xs[i][tid] = v;
        }
        __syncthreads();
        float acc[8] = {0,0,0,0,0,0,0,0};
        const float* W1b = W1 + DD * DD;
        #pragma unroll 4
        for (int d = 0; d < DD; d++) {
            float w = W1b[d * DD + tid];
            #pragma unroll
            for (int i = 0; i < 8; i++) acc[i] = fmaf(xs[i][d], w, acc[i]);
        }
        #pragma unroll
        for (int i = 0; i < 8; i++) {
            float v = acc[i] * kf;
            tt[tid][i] = make_float2(v, __expf(v));
        }
        __syncthreads();
        #pragma unroll
        for (int it = 0; it < 8; it++) {
            int idx = tid + DD * it;
            int f = idx >> 3, pl = idx & 7;
            g_w[(b * DD + f) * NP + p0 + pl] = tt[f][pl];
        }
        if (tid < 8) {
            int p = p0 + tid;
            float4 o = make_float4(0.f, 0.f, 0.f, 0.f);
            if (p < np) {
                int s = cp[b] + p;
                float x = pos_p[s*3+0], y = pos_p[s*3+1], z = pos_p[s*3+2];
                o = make_float4(x, y, z, x*x + y*y + z*z);
            }
            g_xp[r0 + tid] = o;
        }
    }
}

// ---------------- main: tf32 MMA, 2 l-rows per block ----------------
__global__ __launch_bounds__(256, 2) void k_main(
    const float* __restrict__ W_pi, const float* __restrict__ b_pi,
    const float* __restrict__ W_sg, const float* __restrict__ b_sg,
    const float* __restrict__ W_mu, const float* __restrict__ b_mu,
    const int* __restrict__ num_l, const int* __restrict__ num_p,
    float* __restrict__ out)
{
    extern __shared__ char smem[];
    float2* ueu_s = (float2*)(smem + SM_UEU);   // [2*DD] {u, eu}
    uint2*  Bs    = (uint2*)(smem + SM_BS);     // [16 ks][4 nt][32 lane] tf32 pair
    float*  Csm   = (float*)(smem + SM_CSM);    // [512 rows][CPAD]
    float*  bias  = (float*)(smem + SM_BIAS);

    const int tid = threadIdx.x;
    const int bl0 = blockIdx.x * 2;
    const int b   = bl0 / NL;
    const int l0  = bl0 % NL;

    // --- stage {u, exp(u)} for both l rows (contiguous in g_ueu) ---
    ueu_s[tid] = g_ueu[bl0 * DD + tid];

    // --- build B fragments (tf32) for all 16 k-steps x 4 n-tiles ---
    for (int s = tid; s < 2048; s += 256) {
        int lane_s = s & 31, nt = (s >> 5) & 3, ks = s >> 7;
        int tg_s = lane_s & 3, gid_s = lane_s >> 2;
        int j  = 8*nt + gid_s;
        int da = 8*ks + tg_s;
        float v0 = 0.f, v1 = 0.f;
        if (j < 10)      { v0 = W_pi[da*10 + j];        v1 = W_pi[(da+4)*10 + j]; }
        else if (j < 20) { v0 = W_sg[da*10 + (j-10)];   v1 = W_sg[(da+4)*10 + (j-10)]; }
        else if (j < 30) { v0 = W_mu[da*10 + (j-20)];   v1 = W_mu[(da+4)*10 + (j-20)]; }
        uint2 q; q.x = cvt_tf32(v0); q.y = cvt_tf32(v1);
        Bs[s] = q;
    }
    if (tid < 10) {
        bias[tid     ] = b_pi[tid];
        bias[tid + 10] = b_sg[tid];
        bias[tid + 20] = b_mu[tid];
    }
    __syncthreads();

    const int lane = tid & 31, wid = tid >> 5;
    const int tg = lane & 3, gid = lane >> 2;
    const int pbase = wid * 32;
    const float2* __restrict__ gw = g_w + (size_t)b * DD * NP;

    float C[2][2][4][4];   // [l][mtile][ntile][reg]
    #pragma unroll
    for (int l = 0; l < 2; l++)
        #pragma unroll
        for (int mt = 0; mt < 2; mt++)
            #pragma unroll
            for (int nt = 0; nt < 4; nt++)
                #pragma unroll
                for (int r = 0; r < 4; r++) C[l][mt][nt][r] = 0.f;

    #pragma unroll 1
    for (int ks = 0; ks < 16; ks++) {
        const int d0 = 8*ks + tg, d1 = d0 + 4;

        // w loads: 8 independent LDG.64 (rows gid, gid+8, gid+16, gid+24; d0 & d1)
        float2 w0[4], w1[4];
        #pragma unroll
        for (int r = 0; r < 4; r++) {
            int p = pbase + 8*r + gid;
            w0[r] = gw[d0*NP + p];
            w1[r] = gw[d1*NP + p];
        }
        // u for both l rows, both d columns
        float2 u00 = ueu_s[d0],      u01 = ueu_s[d1];
        float2 u10 = ueu_s[DD + d0], u11 = ueu_s[DD + d1];
        // B fragments
        uint32_t bb[4][2];
        #pragma unroll
        for (int nt = 0; nt < 4; nt++) {
            uint2 q = Bs[((ks*4 + nt) << 5) + lane];
            bb[nt][0] = q.x; bb[nt][1] = q.y;
        }

        #pragma unroll
        for (int l = 0; l < 2; l++) {
            float2 ua = l ? u10 : u00;
            float2 ub = l ? u11 : u01;
            #pragma unroll
            for (int mt = 0; mt < 2; mt++) {
                uint32_t a[4];
                a[0] = cvt_tf32(elu2(ua, w0[mt*2 + 0]));
                a[1] = cvt_tf32(elu2(ua, w0[mt*2 + 1]));
                a[2] = cvt_tf32(elu2(ub, w1[mt*2 + 0]));
                a[3] = cvt_tf32(elu2(ub, w1[mt*2 + 1]));
                #pragma unroll
                for (int nt = 0; nt < 4; nt++)
                    mma8(C[l][mt][nt], a, bb[nt]);
            }
        }
    }

    // --- scatter C fragments to padded smem ---
    #pragma unroll
    for (int l = 0; l < 2; l++)
        #pragma unroll
        for (int mt = 0; mt < 2; mt++)
            #pragma unroll
            for (int nt = 0; nt < 4; nt++) {
                int prow = l*256 + pbase + mt*16 + gid;
                int col  = 8*nt + 2*tg;
                *(float2*)&Csm[prow*CPAD + col]       = make_float2(C[l][mt][nt][0], C[l][mt][nt][1]);
                *(float2*)&Csm[(prow+8)*CPAD + col]   = make_float2(C[l][mt][nt][2], C[l][mt][nt][3]);
            }
    __syncthreads();

    // --- per-pair epilogue: p = tid, two l rows ---
    const int p  = tid;
    const int mp = (p < num_p[b]);
    const int nl = num_l[b];
    const float4 xp = g_xp[b * NP + p];

    #pragma unroll
    for (int l = 0; l < 2; l++) {
        const int bl = bl0 + l;
        const float m = (l0 + l < nl && mp) ? 1.f : 0.f;
        const float* row = &Csm[(l*256 + p) * CPAD];

        float z[30];
        #pragma unroll
        for (int jj = 0; jj < 15; jj++) {
            float2 q = *(const float2*)&row[2*jj];
            z[2*jj] = q.x; z[2*jj+1] = q.y;
        }

        float zmax = -1e30f;
        #pragma unroll
        for (int j = 0; j < 10; j++) { z[j] += bias[j]; zmax = fmaxf(zmax, z[j]); }
        float ssum = 0.f;
        #pragma unroll
        for (int j = 0; j < 10; j++) { float e = __expf(z[j] - zmax); z[j] = e; ssum += e; }
        float inv = m / ssum;

        const int base = (bl * NP + p) * 10;
        float2* opi = (float2*)(out + PI_OFF + base);
        float2* osg = (float2*)(out + SG_OFF + base);
        float2* omu = (float2*)(out + MU_OFF + base);
        #pragma unroll
        for (int j = 0; j < 5; j++)
            opi[j] = make_float2(z[2*j] * inv, z[2*j+1] * inv);
        #pragma unroll
        for (int j = 0; j < 10; j++) {
            float t = z[10 + j] + bias[10 + j];
            float e = (t > 0.f) ? t : (__expf(t) - 1.f);
            z[10 + j] = (e + 1.1f) * m;
        }
        #pragma unroll
        for (int j = 0; j < 5; j++) osg[j] = make_float2(z[10+2*j], z[11+2*j]);
        #pragma unroll
        for (int j = 0; j < 10; j++) {
            float t = z[20 + j] + bias[20 + j];
            float e = (t > 0.f) ? t : (__expf(t) - 1.f);
            z[20 + j] = (e + 1.0f) * m;
        }
        #pragma unroll
        for (int j = 0; j < 5; j++) omu[j] = make_float2(z[20+2*j], z[21+2*j]);

        float4 xl = g_xl[bl];
        float d2 = xl.w + xp.w - 2.f * (xl.x*xp.x + xl.y*xp.y + xl.z*xp.z);
        out[DI_OFF + bl * NP + p] = sqrtf(fmaxf(d2, 0.f)) * m;
        out[CM_OFF + bl * NP + p] = m;
    }
}

extern "C" void kernel_launch(void* const* d_in, const int* in_sizes, int n_in,
                              void* d_out, int out_size)
{
    int s = 0;
    if (n_in >= 20 && in_sizes[6] == 1 && in_sizes[7] == 1) s = 2;

    const float* hl    = (const float*)d_in[0];
    const float* hp    = (const float*)d_in[1];
    const float* pos_l = (const float*)d_in[2];
    const float* pos_p = (const float*)d_in[3];
    const int*   num_l = (const int*)  d_in[4];
    const int*   num_p = (const int*)  d_in[5];
    const float* W1    = (const float*)d_in[6 + s];
    const float* b1    = (const float*)d_in[7 + s];
    const float* gamma = (const float*)d_in[8 + s];
    const float* beta  = (const float*)d_in[9 + s];
    const float* mean  = (const float*)d_in[10 + s];
    const float* var   = (const float*)d_in[11 + s];
    const float* W_pi  = (const float*)d_in[12 + s];
    const float* b_pi  = (const float*)d_in[13 + s];
    const float* W_sg  = (const float*)d_in[14 + s];
    const float* b_sg  = (const float*)d_in[15 + s];
    const float* W_mu  = (const float*)d_in[16 + s];
    const float* b_mu  = (const float*)d_in[17 + s];
    float* out = (float*)d_out;

    cudaFuncSetAttribute(k_main, cudaFuncAttributeMaxDynamicSharedMemorySize, SM_TOTAL);

    k_pre <<<NROW_L/8 + NROW_P/8, DD>>>(hl, hp, pos_l, pos_p, num_l, num_p,
                                        W1, b1, gamma, beta, mean, var);
    k_main<<<BB * NL / 2, 256, SM_TOTAL>>>(W_pi, b_pi, W_sg, b_sg, W_mu, b_mu,
                                           num_l, num_p, out);
}